// round 6
// baseline (speedup 1.0000x reference)
#include <cuda_runtime.h>
#include <cuda_bf16.h>
#include <math.h>
#include <stddef.h>
#include <stdint.h>

// Problem constants
#define D_MODEL 1024
#define DK      1024
#define BATCH   4
#define SEQ     2048
#define BT      (BATCH * SEQ)   // 8192

typedef __nv_bfloat16 bf16;

// ===========================================================================
// Scratch (__device__ globals; allocation-free)
// ===========================================================================
__device__ bf16 g_xhi[(size_t)BT * D_MODEL];
__device__ bf16 g_xlo[(size_t)BT * D_MODEL];
__device__ bf16 g_wthi[3][(size_t)D_MODEL * DK];   // W^T, (dk, d_model) K-major
__device__ bf16 g_wtlo[3][(size_t)D_MODEL * DK];
__device__ bf16 g_QKVhi[3][(size_t)BT * DK];       // [0]=Q, [1]=K, [2]=V
__device__ bf16 g_QKVlo[3][(size_t)BT * DK];
__device__ bf16 g_Vthi[(size_t)BATCH * DK * SEQ];  // per batch: (dk, t)
__device__ bf16 g_Vtlo[(size_t)BATCH * DK * SEQ];
__device__ float g_S[(size_t)BATCH * SEQ * SEQ];
__device__ bf16 g_Phi[(size_t)BATCH * SEQ * SEQ];
__device__ bf16 g_Plo[(size_t)BATCH * SEQ * SEQ];

__device__ __forceinline__ void split_f32(float v, bf16& h, bf16& l) {
    h = __float2bfloat16(v);
    l = __float2bfloat16(v - __bfloat162float(h));
}

__device__ __forceinline__ uint32_t smem_to_u32(const void* p) {
    uint32_t a;
    asm("{ .reg .u64 t; cvta.to.shared.u64 t, %1; cvt.u32.u64 %0, t; }" : "=r"(a) : "l"(p));
    return a;
}

__device__ __forceinline__ void ldm_x4(uint32_t& r0, uint32_t& r1, uint32_t& r2, uint32_t& r3,
                                       uint32_t addr) {
    asm volatile("ldmatrix.sync.aligned.m8n8.x4.shared.b16 {%0,%1,%2,%3}, [%4];"
                 : "=r"(r0), "=r"(r1), "=r"(r2), "=r"(r3) : "r"(addr));
}

__device__ __forceinline__ void mma_bf16(float* c, const uint32_t* a, const uint32_t* b) {
    asm volatile("mma.sync.aligned.m16n8k16.row.col.f32.bf16.bf16.f32 "
                 "{%0,%1,%2,%3}, {%4,%5,%6,%7}, {%8,%9}, {%0,%1,%2,%3};"
                 : "+f"(c[0]), "+f"(c[1]), "+f"(c[2]), "+f"(c[3])
                 : "r"(a[0]), "r"(a[1]), "r"(a[2]), "r"(a[3]), "r"(b[0]), "r"(b[1]));
}

#define CP_ASYNC16(dst, src) \
    asm volatile("cp.async.cg.shared.global [%0], [%1], 16;" :: "r"(dst), "l"(src) : "memory")
#define CP_COMMIT() asm volatile("cp.async.commit_group;" ::: "memory")
#define CP_WAIT0()  asm volatile("cp.async.wait_group 0;" ::: "memory")
#define CP_WAIT1()  asm volatile("cp.async.wait_group 1;" ::: "memory")

// Swizzled SMEM address: row*64B, chunk' = chunk ^ ((row>>1)&3) -> conflict-free ldmatrix.
__device__ __forceinline__ uint32_t sw(uint32_t base, int row, int ch) {
    return base + row * 64 + ((ch ^ ((row >> 1) & 3)) << 4);
}

// ===========================================================================
// Elementwise split: f32 -> (hi, lo) bf16
// ===========================================================================
__global__ __launch_bounds__(256)
void split_kernel(const float* __restrict__ in, bf16* __restrict__ hi, bf16* __restrict__ lo)
{
    size_t i = ((size_t)blockIdx.x * 256 + threadIdx.x) * 4;
    float4 v = *(const float4*)(in + i);
    bf16 h0, l0, h1, l1, h2, l2, h3, l3;
    split_f32(v.x, h0, l0); split_f32(v.y, h1, l1);
    split_f32(v.z, h2, l2); split_f32(v.w, h3, l3);
    uint32_t hp0 = (uint32_t)__bfloat16_as_ushort(h0) | ((uint32_t)__bfloat16_as_ushort(h1) << 16);
    uint32_t hp1 = (uint32_t)__bfloat16_as_ushort(h2) | ((uint32_t)__bfloat16_as_ushort(h3) << 16);
    uint32_t lp0 = (uint32_t)__bfloat16_as_ushort(l0) | ((uint32_t)__bfloat16_as_ushort(l1) << 16);
    uint32_t lp1 = (uint32_t)__bfloat16_as_ushort(l2) | ((uint32_t)__bfloat16_as_ushort(l3) << 16);
    *(uint2*)(hi + i) = make_uint2(hp0, hp1);
    *(uint2*)(lo + i) = make_uint2(lp0, lp1);
}

// ===========================================================================
// W (d_model, dk) f32 -> W^T (dk, d_model) split bf16
// ===========================================================================
__global__ __launch_bounds__(256)
void wt_split_kernel(const float* __restrict__ W, bf16* __restrict__ Whi, bf16* __restrict__ Wlo)
{
    __shared__ float tile[32][33];
    int x = blockIdx.x * 32 + threadIdx.x;
    int y = blockIdx.y * 32 + threadIdx.y;
    #pragma unroll
    for (int i = 0; i < 32; i += 8)
        tile[threadIdx.y + i][threadIdx.x] = W[(size_t)(y + i) * DK + x];
    __syncthreads();
    int x2 = blockIdx.y * 32 + threadIdx.x;
    int y2 = blockIdx.x * 32 + threadIdx.y;
    #pragma unroll
    for (int i = 0; i < 32; i += 8) {
        float v = tile[threadIdx.x][threadIdx.y + i];
        bf16 h, l; split_f32(v, h, l);
        Whi[(size_t)(y2 + i) * D_MODEL + x2] = h;
        Wlo[(size_t)(y2 + i) * D_MODEL + x2] = l;
    }
}

// ===========================================================================
// V (t, dk) split bf16 -> V^T (dk, t) split bf16, per batch
// ===========================================================================
__global__ __launch_bounds__(256)
void v_transpose_kernel(const bf16* __restrict__ Vhi, const bf16* __restrict__ Vlo,
                        bf16* __restrict__ Vthi, bf16* __restrict__ Vtlo)
{
    __shared__ bf16 th[32][34];
    __shared__ bf16 tl[32][34];
    const size_t in_base  = (size_t)blockIdx.z * SEQ * DK;
    const size_t out_base = (size_t)blockIdx.z * DK * SEQ;
    int n = blockIdx.x * 32 + threadIdx.x;
    int t = blockIdx.y * 32 + threadIdx.y;
    #pragma unroll
    for (int i = 0; i < 32; i += 8) {
        th[threadIdx.y + i][threadIdx.x] = Vhi[in_base + (size_t)(t + i) * DK + n];
        tl[threadIdx.y + i][threadIdx.x] = Vlo[in_base + (size_t)(t + i) * DK + n];
    }
    __syncthreads();
    int t2 = blockIdx.y * 32 + threadIdx.x;
    int n2 = blockIdx.x * 32 + threadIdx.y;
    #pragma unroll
    for (int i = 0; i < 32; i += 8) {
        Vthi[out_base + (size_t)(n2 + i) * SEQ + t2] = th[threadIdx.x][threadIdx.y + i];
        Vtlo[out_base + (size_t)(n2 + i) * SEQ + t2] = tl[threadIdx.x][threadIdx.y + i];
    }
}

// ===========================================================================
// HMMA split-bf16 GEMM, 256x128 CTA tile, 3-stage cp.async ring
//   C[M,N] = scale * (A @ B^T); acc = Ah@Bh + Al@Bh + Ah@Bl
//   256 threads, 8 warps (4xM, 2xN), warp tile 64x64, KC=32.
//   SMEM/stage: A 256x32 hi+lo (32KB) + B 128x32 hi+lo (16KB) = 48KB.
//   mode 0: f32 out * scale; mode 1: split bf16 out (Chi/Clo + z*sCbf)
//   causal: skip CTA if bn > bm+255;  trik: K limited to bm+256.
// ===========================================================================
#define STG_B   49152
#define T_A0    0
#define T_A1    16384
#define T_B0    32768
#define T_B1    40960
#define GEMM_SMEM (3 * STG_B)

__device__ __forceinline__ void load_stage(uint32_t st,
    const bf16* Ahi, const bf16* Alo, const bf16* Bhi, const bf16* Blo,
    int K, int bm, int bn, int k0, int tid)
{
    // A: 256 rows x 32 cols (hi+lo)
    #pragma unroll
    for (int i = 0; i < 4; i++) {
        const int f = tid + (i << 8);
        const int r = f >> 2;
        const int c = f & 3;
        const uint32_t so = (uint32_t)(r * 64 + ((c ^ ((r >> 1) & 3)) << 4));
        const size_t ga = (size_t)(bm + r) * K + k0 + c * 8;
        CP_ASYNC16(st + T_A0 + so, Ahi + ga);
        CP_ASYNC16(st + T_A1 + so, Alo + ga);
    }
    // B: 128 rows x 32 cols (hi+lo)
    #pragma unroll
    for (int i = 0; i < 2; i++) {
        const int f = tid + (i << 8);
        const int r = f >> 2;
        const int c = f & 3;
        const uint32_t so = (uint32_t)(r * 64 + ((c ^ ((r >> 1) & 3)) << 4));
        const size_t gb = (size_t)(bn + r) * K + k0 + c * 8;
        CP_ASYNC16(st + T_B0 + so, Bhi + gb);
        CP_ASYNC16(st + T_B1 + so, Blo + gb);
    }
}

__global__ __launch_bounds__(256, 1)
void gemm_nt_hmma(const bf16* __restrict__ Ahi, const bf16* __restrict__ Alo,
                  const bf16* __restrict__ Bhi, const bf16* __restrict__ Blo,
                  int K, size_t sA, size_t sB,
                  int mode, float scale, int causal, int trik,
                  float* __restrict__ Cf, int ldc, size_t sC,
                  bf16* __restrict__ Chi, bf16* __restrict__ Clo, size_t sCbf)
{
    const int bm = blockIdx.y * 256;
    const int bn = blockIdx.x * 128;
    const int b  = blockIdx.z;
    if (causal && bn > bm + 255) return;

    Ahi += (size_t)b * sA;  Alo += (size_t)b * sA;
    Bhi += (size_t)b * sB;  Blo += (size_t)b * sB;

    extern __shared__ char smem[];
    const uint32_t sb = smem_to_u32(smem);

    const int tid  = threadIdx.x;
    const int lane = tid & 31;
    const int wid  = tid >> 5;
    const int wm   = wid & 3;    // 0..3 -> 64-row slice
    const int wn   = wid >> 2;   // 0..1 -> 64-col slice

    float acc[4][8][4];
    #pragma unroll
    for (int mt = 0; mt < 4; mt++)
        #pragma unroll
        for (int nt = 0; nt < 8; nt++)
            #pragma unroll
            for (int j = 0; j < 4; j++) acc[mt][nt][j] = 0.0f;

    int Keff = trik ? (bm + 256 < K ? bm + 256 : K) : K;
    const int nc = Keff >> 5;   // >= 8 always here

    load_stage(sb + 0 * STG_B, Ahi, Alo, Bhi, Blo, K, bm, bn, 0, tid);
    CP_COMMIT();
    load_stage(sb + 1 * STG_B, Ahi, Alo, Bhi, Blo, K, bm, bn, 32, tid);
    CP_COMMIT();

    int buf = 0;
    for (int c = 0; c < nc; c++) {
        if (c + 1 < nc) CP_WAIT1(); else CP_WAIT0();
        __syncthreads();

        const uint32_t st  = sb + buf * STG_B;
        const uint32_t aA0 = st + T_A0, aA1 = st + T_A1;
        const uint32_t aB0 = st + T_B0, aB1 = st + T_B1;

        #pragma unroll
        for (int ks = 0; ks < 2; ks++) {
            const int lrow = lane & 15;
            const int ch   = ks * 2 + (lane >> 4);

            uint32_t ah[4][4], aw[4][4], bb[8][2];

            #pragma unroll
            for (int mt = 0; mt < 4; mt++) {
                const int r = wm * 64 + mt * 16 + lrow;
                ldm_x4(ah[mt][0], ah[mt][1], ah[mt][2], ah[mt][3], sw(aA0, r, ch));
                ldm_x4(aw[mt][0], aw[mt][1], aw[mt][2], aw[mt][3], sw(aA1, r, ch));
            }
            #pragma unroll
            for (int np = 0; np < 4; np++) {
                const int r = wn * 64 + np * 16 + lrow;
                uint32_t r0, r1, r2, r3;
                ldm_x4(r0, r1, r2, r3, sw(aB0, r, ch));
                bb[2*np][0] = r0; bb[2*np+1][0] = r1;
                bb[2*np][1] = r2; bb[2*np+1][1] = r3;
            }
            // pass 1: A_hi @ B_hi
            #pragma unroll
            for (int mt = 0; mt < 4; mt++)
                #pragma unroll
                for (int nt = 0; nt < 8; nt++)
                    mma_bf16(acc[mt][nt], ah[mt], bb[nt]);
            // pass 2: A_lo @ B_hi
            #pragma unroll
            for (int mt = 0; mt < 4; mt++)
                #pragma unroll
                for (int nt = 0; nt < 8; nt++)
                    mma_bf16(acc[mt][nt], aw[mt], bb[nt]);

            // B_lo fragments (reuse bb)
            #pragma unroll
            for (int np = 0; np < 4; np++) {
                const int r = wn * 64 + np * 16 + lrow;
                uint32_t r0, r1, r2, r3;
                ldm_x4(r0, r1, r2, r3, sw(aB1, r, ch));
                bb[2*np][0] = r0; bb[2*np+1][0] = r1;
                bb[2*np][1] = r2; bb[2*np+1][1] = r3;
            }
            // pass 3: A_hi @ B_lo
            #pragma unroll
            for (int mt = 0; mt < 4; mt++)
                #pragma unroll
                for (int nt = 0; nt < 8; nt++)
                    mma_bf16(acc[mt][nt], ah[mt], bb[nt]);
        }

        if (c + 2 < nc) {
            int nb = buf + 2; if (nb >= 3) nb -= 3;
            load_stage(sb + nb * STG_B, Ahi, Alo, Bhi, Blo, K, bm, bn, (c + 2) << 5, tid);
            CP_COMMIT();
        }
        buf = (buf == 2) ? 0 : buf + 1;
        __syncthreads();
    }

    // ---- epilogue ----
    const int tr = lane >> 2;
    const int tc = (lane & 3) * 2;
    if (mode == 0) {
        float* Cb = Cf + (size_t)b * sC;
        #pragma unroll
        for (int mt = 0; mt < 4; mt++) {
            #pragma unroll
            for (int nt = 0; nt < 8; nt++) {
                const int row = bm + wm * 64 + mt * 16 + tr;
                const int col = bn + wn * 64 + nt * 8 + tc;
                float2 v0 = make_float2(acc[mt][nt][0] * scale, acc[mt][nt][1] * scale);
                float2 v1 = make_float2(acc[mt][nt][2] * scale, acc[mt][nt][3] * scale);
                *(float2*)&Cb[(size_t)row * ldc + col]       = v0;
                *(float2*)&Cb[(size_t)(row + 8) * ldc + col] = v1;
            }
        }
    } else {
        bf16* Hb = Chi + (size_t)b * sCbf;
        bf16* Lb = Clo + (size_t)b * sCbf;
        #pragma unroll
        for (int mt = 0; mt < 4; mt++) {
            #pragma unroll
            for (int nt = 0; nt < 8; nt++) {
                const int row = bm + wm * 64 + mt * 16 + tr;
                const int col = bn + wn * 64 + nt * 8 + tc;
                #pragma unroll
                for (int h = 0; h < 2; h++) {
                    float v0 = acc[mt][nt][2*h + 0] * scale;
                    float v1 = acc[mt][nt][2*h + 1] * scale;
                    bf16 h0, l0, h1, l1;
                    split_f32(v0, h0, l0); split_f32(v1, h1, l1);
                    uint32_t hp = (uint32_t)__bfloat16_as_ushort(h0) |
                                  ((uint32_t)__bfloat16_as_ushort(h1) << 16);
                    uint32_t lp = (uint32_t)__bfloat16_as_ushort(l0) |
                                  ((uint32_t)__bfloat16_as_ushort(l1) << 16);
                    *(uint32_t*)&Hb[(size_t)(row + 8*h) * ldc + col] = hp;
                    *(uint32_t*)&Lb[(size_t)(row + 8*h) * ldc + col] = lp;
                }
            }
        }
    }
}

// ===========================================================================
// Causal softmax: reads g_S f32 row (2 passes, exp cached in regs),
// writes P as split bf16 (+zero tail)
// ===========================================================================
__global__ __launch_bounds__(256)
void softmax_causal_kernel()
{
    const int q = blockIdx.x;
    const int b = blockIdx.y;
    const size_t base = ((size_t)b * SEQ + q) * SEQ;
    const float* row = g_S + base;
    const int len = q + 1;

    const int tid = threadIdx.x, lane = tid & 31, w = tid >> 5;
    __shared__ float red_max[8], red_sum[8], s_m, s_inv;

    float m = -INFINITY;
    for (int j = tid; j < len; j += 256) m = fmaxf(m, row[j]);
    #pragma unroll
    for (int o = 16; o; o >>= 1) m = fmaxf(m, __shfl_xor_sync(0xffffffffu, m, o));
    if (lane == 0) red_max[w] = m;
    __syncthreads();
    if (w == 0) {
        float v = (lane < 8) ? red_max[lane] : -INFINITY;
        #pragma unroll
        for (int o = 4; o; o >>= 1) v = fmaxf(v, __shfl_xor_sync(0xffffffffu, v, o));
        if (lane == 0) s_m = v;
    }
    __syncthreads();
    m = s_m;

    float e[8];
    float s = 0.0f;
    {
        int idx = 0;
        for (int j = tid; j < len; j += 256, idx++) {
            float v = __expf(row[j] - m);
            e[idx] = v;
            s += v;
        }
    }
    #pragma unroll
    for (int o = 16; o; o >>= 1) s += __shfl_xor_sync(0xffffffffu, s, o);
    if (lane == 0) red_sum[w] = s;
    __syncthreads();
    if (w == 0) {
        float v = (lane < 8) ? red_sum[lane] : 0.0f;
        #pragma unroll
        for (int o = 4; o; o >>= 1) v += __shfl_xor_sync(0xffffffffu, v, o);
        if (lane == 0) s_inv = 1.0f / v;
    }
    __syncthreads();
    const float inv = s_inv;

    {
        int idx = 0;
        for (int j = tid; j < SEQ; j += 256) {
            float p;
            if (j < len) { p = e[idx] * inv; idx++; } else p = 0.0f;
            bf16 h, l; split_f32(p, h, l);
            g_Phi[base + j] = h;
            g_Plo[base + j] = l;
        }
    }
}

// ===========================================================================
// Launch
// ===========================================================================
extern "C" void kernel_launch(void* const* d_in, const int* in_sizes, int n_in,
                              void* d_out, int out_size)
{
    const float* x  = (const float*)d_in[0];
    const float* Wq = (const float*)d_in[1];
    const float* Wk = (const float*)d_in[2];
    const float* Wv = (const float*)d_in[3];
    float* out = (float*)d_out;

    cudaFuncSetAttribute(gemm_nt_hmma, cudaFuncAttributeMaxDynamicSharedMemorySize, GEMM_SMEM);

    bf16 *xhi, *xlo, *wthi, *wtlo, *qkvhi, *qkvlo, *Vthi, *Vtlo, *Phi, *Plo;
    float *Sp;
    cudaGetSymbolAddress((void**)&xhi, g_xhi);    cudaGetSymbolAddress((void**)&xlo, g_xlo);
    cudaGetSymbolAddress((void**)&wthi, g_wthi);  cudaGetSymbolAddress((void**)&wtlo, g_wtlo);
    cudaGetSymbolAddress((void**)&qkvhi, g_QKVhi); cudaGetSymbolAddress((void**)&qkvlo, g_QKVlo);
    cudaGetSymbolAddress((void**)&Vthi, g_Vthi);  cudaGetSymbolAddress((void**)&Vtlo, g_Vtlo);
    cudaGetSymbolAddress((void**)&Phi, g_Phi);    cudaGetSymbolAddress((void**)&Plo, g_Plo);
    cudaGetSymbolAddress((void**)&Sp, g_S);

    const size_t WSZ  = (size_t)D_MODEL * DK;
    const size_t QKVS = (size_t)BT * DK;

    // 1) input splits / transposes
    split_kernel<<<(BT * D_MODEL) / (256 * 4), 256>>>(x, xhi, xlo);
    {
        dim3 g(DK / 32, D_MODEL / 32), blk(32, 8);
        wt_split_kernel<<<g, blk>>>(Wq, wthi + 0 * WSZ, wtlo + 0 * WSZ);
        wt_split_kernel<<<g, blk>>>(Wk, wthi + 1 * WSZ, wtlo + 1 * WSZ);
        wt_split_kernel<<<g, blk>>>(Wv, wthi + 2 * WSZ, wtlo + 2 * WSZ);
    }

    // 2) merged QKV projection: z in {0,1,2} selects W and output slice
    {
        dim3 grid(DK / 128, BT / 256, 3);
        gemm_nt_hmma<<<grid, 256, GEMM_SMEM>>>(xhi, xlo, wthi, wtlo,
            D_MODEL, 0, WSZ, 1, 1.0f, 0, 0,
            nullptr, DK, 0, qkvhi, qkvlo, QKVS);
    }

    // 3) V transpose per batch: (t, dk) -> (dk, t)
    {
        dim3 g(DK / 32, SEQ / 32, BATCH), blk(32, 8);
        v_transpose_kernel<<<g, blk>>>(qkvhi + 2 * QKVS, qkvlo + 2 * QKVS, Vthi, Vtlo);
    }

    // 4) scores = (1/32) * Q @ K^T, causal block skip (256-row granularity)
    {
        dim3 grid(SEQ / 128, SEQ / 256, BATCH);
        gemm_nt_hmma<<<grid, 256, GEMM_SMEM>>>(qkvhi, qkvlo, qkvhi + QKVS, qkvlo + QKVS,
            DK, (size_t)SEQ * DK, (size_t)SEQ * DK, 0, 1.0f / 32.0f, 1, 0,
            Sp, SEQ, (size_t)SEQ * SEQ, nullptr, nullptr, 0);
    }

    // 5) causal softmax -> split bf16 P (zero tail)
    softmax_causal_kernel<<<dim3(SEQ, BATCH), 256>>>();

    // 6) out = P @ V  (= P @ (V^T)^T), K truncated per diagonal
    {
        dim3 grid(DK / 128, SEQ / 256, BATCH);
        gemm_nt_hmma<<<grid, 256, GEMM_SMEM>>>(Phi, Plo, Vthi, Vtlo,
            SEQ, (size_t)SEQ * SEQ, (size_t)DK * SEQ, 0, 1.0f, 0, 1,
            out, DK, (size_t)SEQ * DK, nullptr, nullptr, 0);
    }
}

// round 7
// speedup vs baseline: 1.0272x; 1.0272x over previous
#include <cuda_runtime.h>
#include <cuda_bf16.h>
#include <math.h>
#include <stddef.h>
#include <stdint.h>

// Problem constants
#define D_MODEL 1024
#define DK      1024
#define BATCH   4
#define SEQ     2048
#define BT      (BATCH * SEQ)   // 8192

typedef __nv_bfloat16 bf16;

// ===========================================================================
// Scratch (__device__ globals; allocation-free)
// ===========================================================================
__device__ bf16 g_xhi[(size_t)BT * D_MODEL];
__device__ bf16 g_xlo[(size_t)BT * D_MODEL];
__device__ bf16 g_wthi[3][(size_t)D_MODEL * DK];   // W^T, (dk, d_model) K-major
__device__ bf16 g_wtlo[3][(size_t)D_MODEL * DK];
__device__ bf16 g_QKVhi[3][(size_t)BT * DK];       // [0]=Q, [1]=K, [2]=V
__device__ bf16 g_QKVlo[3][(size_t)BT * DK];
__device__ bf16 g_Vthi[(size_t)BATCH * DK * SEQ];  // per batch: (dk, t)
__device__ bf16 g_Vtlo[(size_t)BATCH * DK * SEQ];
__device__ float g_S[(size_t)BATCH * SEQ * SEQ];
__device__ bf16 g_Phi[(size_t)BATCH * SEQ * SEQ];
__device__ bf16 g_Plo[(size_t)BATCH * SEQ * SEQ];

__device__ __forceinline__ void split_f32(float v, bf16& h, bf16& l) {
    h = __float2bfloat16(v);
    l = __float2bfloat16(v - __bfloat162float(h));
}

__device__ __forceinline__ uint32_t smem_to_u32(const void* p) {
    uint32_t a;
    asm("{ .reg .u64 t; cvta.to.shared.u64 t, %1; cvt.u32.u64 %0, t; }" : "=r"(a) : "l"(p));
    return a;
}

__device__ __forceinline__ void ldm_x4(uint32_t& r0, uint32_t& r1, uint32_t& r2, uint32_t& r3,
                                       uint32_t addr) {
    asm volatile("ldmatrix.sync.aligned.m8n8.x4.shared.b16 {%0,%1,%2,%3}, [%4];"
                 : "=r"(r0), "=r"(r1), "=r"(r2), "=r"(r3) : "r"(addr));
}

__device__ __forceinline__ void mma_bf16(float* c, const uint32_t* a, const uint32_t* b) {
    asm volatile("mma.sync.aligned.m16n8k16.row.col.f32.bf16.bf16.f32 "
                 "{%0,%1,%2,%3}, {%4,%5,%6,%7}, {%8,%9}, {%0,%1,%2,%3};"
                 : "+f"(c[0]), "+f"(c[1]), "+f"(c[2]), "+f"(c[3])
                 : "r"(a[0]), "r"(a[1]), "r"(a[2]), "r"(a[3]), "r"(b[0]), "r"(b[1]));
}

#define CP_ASYNC16(dst, src) \
    asm volatile("cp.async.cg.shared.global [%0], [%1], 16;" :: "r"(dst), "l"(src) : "memory")
#define CP_COMMIT() asm volatile("cp.async.commit_group;" ::: "memory")
#define CP_WAIT0()  asm volatile("cp.async.wait_group 0;" ::: "memory")
#define CP_WAIT1()  asm volatile("cp.async.wait_group 1;" ::: "memory")

// Swizzled SMEM address: row*64B, chunk' = chunk ^ ((row>>1)&3) -> conflict-free ldmatrix.
__device__ __forceinline__ uint32_t sw(uint32_t base, int row, int ch) {
    return base + row * 64 + ((ch ^ ((row >> 1) & 3)) << 4);
}

// ===========================================================================
// Elementwise split: f32 -> (hi, lo) bf16
// ===========================================================================
__global__ __launch_bounds__(256)
void split_kernel(const float* __restrict__ in, bf16* __restrict__ hi, bf16* __restrict__ lo)
{
    size_t i = ((size_t)blockIdx.x * 256 + threadIdx.x) * 4;
    float4 v = *(const float4*)(in + i);
    bf16 h0, l0, h1, l1, h2, l2, h3, l3;
    split_f32(v.x, h0, l0); split_f32(v.y, h1, l1);
    split_f32(v.z, h2, l2); split_f32(v.w, h3, l3);
    uint32_t hp0 = (uint32_t)__bfloat16_as_ushort(h0) | ((uint32_t)__bfloat16_as_ushort(h1) << 16);
    uint32_t hp1 = (uint32_t)__bfloat16_as_ushort(h2) | ((uint32_t)__bfloat16_as_ushort(h3) << 16);
    uint32_t lp0 = (uint32_t)__bfloat16_as_ushort(l0) | ((uint32_t)__bfloat16_as_ushort(l1) << 16);
    uint32_t lp1 = (uint32_t)__bfloat16_as_ushort(l2) | ((uint32_t)__bfloat16_as_ushort(l3) << 16);
    *(uint2*)(hi + i) = make_uint2(hp0, hp1);
    *(uint2*)(lo + i) = make_uint2(lp0, lp1);
}

// ===========================================================================
// W (d_model, dk) f32 -> W^T (dk, d_model) split bf16
// ===========================================================================
__global__ __launch_bounds__(256)
void wt_split_kernel(const float* __restrict__ W, bf16* __restrict__ Whi, bf16* __restrict__ Wlo)
{
    __shared__ float tile[32][33];
    int x = blockIdx.x * 32 + threadIdx.x;
    int y = blockIdx.y * 32 + threadIdx.y;
    #pragma unroll
    for (int i = 0; i < 32; i += 8)
        tile[threadIdx.y + i][threadIdx.x] = W[(size_t)(y + i) * DK + x];
    __syncthreads();
    int x2 = blockIdx.y * 32 + threadIdx.x;
    int y2 = blockIdx.x * 32 + threadIdx.y;
    #pragma unroll
    for (int i = 0; i < 32; i += 8) {
        float v = tile[threadIdx.x][threadIdx.y + i];
        bf16 h, l; split_f32(v, h, l);
        Whi[(size_t)(y2 + i) * D_MODEL + x2] = h;
        Wlo[(size_t)(y2 + i) * D_MODEL + x2] = l;
    }
}

// ===========================================================================
// V (t, dk) split bf16 -> V^T (dk, t) split bf16, per batch
// ===========================================================================
__global__ __launch_bounds__(256)
void v_transpose_kernel(const bf16* __restrict__ Vhi, const bf16* __restrict__ Vlo,
                        bf16* __restrict__ Vthi, bf16* __restrict__ Vtlo)
{
    __shared__ bf16 th[32][34];
    __shared__ bf16 tl[32][34];
    const size_t in_base  = (size_t)blockIdx.z * SEQ * DK;
    const size_t out_base = (size_t)blockIdx.z * DK * SEQ;
    int n = blockIdx.x * 32 + threadIdx.x;
    int t = blockIdx.y * 32 + threadIdx.y;
    #pragma unroll
    for (int i = 0; i < 32; i += 8) {
        th[threadIdx.y + i][threadIdx.x] = Vhi[in_base + (size_t)(t + i) * DK + n];
        tl[threadIdx.y + i][threadIdx.x] = Vlo[in_base + (size_t)(t + i) * DK + n];
    }
    __syncthreads();
    int t2 = blockIdx.y * 32 + threadIdx.x;
    int n2 = blockIdx.x * 32 + threadIdx.y;
    #pragma unroll
    for (int i = 0; i < 32; i += 8) {
        Vthi[out_base + (size_t)(n2 + i) * SEQ + t2] = th[threadIdx.x][threadIdx.y + i];
        Vtlo[out_base + (size_t)(n2 + i) * SEQ + t2] = tl[threadIdx.x][threadIdx.y + i];
    }
}

// ===========================================================================
// HMMA split-bf16 GEMM, 256x128 CTA tile, 512 threads, 3-stage cp.async ring
//   C[M,N] = scale * (A @ B^T); acc = Ah@Bh + Al@Bh + Ah@Bl
//   16 warps (4xM, 4xN), warp tile 64x32, KC=32. 1 CTA/SM (full regfile).
//   SMEM/stage: A 256x32 hi+lo (32KB) + B 128x32 hi+lo (16KB) = 48KB.
//   mode 0: f32 out * scale; mode 1: split bf16 out (Chi/Clo + z*sCbf)
//   causal: skip CTA if bn > bm+255;  trik: K limited to bm+256.
// ===========================================================================
#define STG_B   49152
#define T_A0    0
#define T_A1    16384
#define T_B0    32768
#define T_B1    40960
#define GEMM_SMEM (3 * STG_B)

__device__ __forceinline__ void load_stage(uint32_t st,
    const bf16* Ahi, const bf16* Alo, const bf16* Bhi, const bf16* Blo,
    int K, int bm, int bn, int k0, int tid)
{
    // A: 256 rows x 32 cols (hi+lo): 1024 uint4 each -> 2 per thread
    #pragma unroll
    for (int i = 0; i < 2; i++) {
        const int f = tid + (i << 9);
        const int r = f >> 2;
        const int c = f & 3;
        const uint32_t so = (uint32_t)(r * 64 + ((c ^ ((r >> 1) & 3)) << 4));
        const size_t ga = (size_t)(bm + r) * K + k0 + c * 8;
        CP_ASYNC16(st + T_A0 + so, Ahi + ga);
        CP_ASYNC16(st + T_A1 + so, Alo + ga);
    }
    // B: 128 rows x 32 cols (hi+lo): 512 uint4 each -> 1 per thread
    {
        const int r = tid >> 2;
        const int c = tid & 3;
        const uint32_t so = (uint32_t)(r * 64 + ((c ^ ((r >> 1) & 3)) << 4));
        const size_t gb = (size_t)(bn + r) * K + k0 + c * 8;
        CP_ASYNC16(st + T_B0 + so, Bhi + gb);
        CP_ASYNC16(st + T_B1 + so, Blo + gb);
    }
}

__global__ __launch_bounds__(512, 1)
void gemm_nt_hmma(const bf16* __restrict__ Ahi, const bf16* __restrict__ Alo,
                  const bf16* __restrict__ Bhi, const bf16* __restrict__ Blo,
                  int K, size_t sA, size_t sB,
                  int mode, float scale, int causal, int trik,
                  float* __restrict__ Cf, int ldc, size_t sC,
                  bf16* __restrict__ Chi, bf16* __restrict__ Clo, size_t sCbf)
{
    const int bm = blockIdx.y * 256;
    const int bn = blockIdx.x * 128;
    const int b  = blockIdx.z;
    if (causal && bn > bm + 255) return;

    Ahi += (size_t)b * sA;  Alo += (size_t)b * sA;
    Bhi += (size_t)b * sB;  Blo += (size_t)b * sB;

    extern __shared__ char smem[];
    const uint32_t sb = smem_to_u32(smem);

    const int tid  = threadIdx.x;
    const int lane = tid & 31;
    const int wid  = tid >> 5;
    const int wm   = wid & 3;    // 0..3 -> 64-row slice
    const int wn   = wid >> 2;   // 0..3 -> 32-col slice

    float acc[4][4][4];
    #pragma unroll
    for (int mt = 0; mt < 4; mt++)
        #pragma unroll
        for (int nt = 0; nt < 4; nt++)
            #pragma unroll
            for (int j = 0; j < 4; j++) acc[mt][nt][j] = 0.0f;

    int Keff = trik ? (bm + 256 < K ? bm + 256 : K) : K;
    const int nc = Keff >> 5;   // >= 8 always here

    load_stage(sb + 0 * STG_B, Ahi, Alo, Bhi, Blo, K, bm, bn, 0, tid);
    CP_COMMIT();
    load_stage(sb + 1 * STG_B, Ahi, Alo, Bhi, Blo, K, bm, bn, 32, tid);
    CP_COMMIT();

    int buf = 0;
    for (int c = 0; c < nc; c++) {
        if (c + 1 < nc) CP_WAIT1(); else CP_WAIT0();
        __syncthreads();

        const uint32_t st  = sb + buf * STG_B;
        const uint32_t aA0 = st + T_A0, aA1 = st + T_A1;
        const uint32_t aB0 = st + T_B0, aB1 = st + T_B1;

        #pragma unroll
        for (int ks = 0; ks < 2; ks++) {
            const int lrow = lane & 15;
            const int ch   = ks * 2 + (lane >> 4);

            uint32_t ah[4][4], aw[4][4], bb[4][2];

            // A_hi fragments
            #pragma unroll
            for (int mt = 0; mt < 4; mt++) {
                const int r = wm * 64 + mt * 16 + lrow;
                ldm_x4(ah[mt][0], ah[mt][1], ah[mt][2], ah[mt][3], sw(aA0, r, ch));
            }
            // B_hi fragments (32 cols = 2 x4 ldmatrix)
            #pragma unroll
            for (int np = 0; np < 2; np++) {
                const int r = wn * 32 + np * 16 + lrow;
                uint32_t r0, r1, r2, r3;
                ldm_x4(r0, r1, r2, r3, sw(aB0, r, ch));
                bb[2*np][0] = r0; bb[2*np+1][0] = r1;
                bb[2*np][1] = r2; bb[2*np+1][1] = r3;
            }
            // pass 1: A_hi @ B_hi
            #pragma unroll
            for (int mt = 0; mt < 4; mt++)
                #pragma unroll
                for (int nt = 0; nt < 4; nt++)
                    mma_bf16(acc[mt][nt], ah[mt], bb[nt]);

            // A_lo fragments, pass 2: A_lo @ B_hi
            #pragma unroll
            for (int mt = 0; mt < 4; mt++) {
                const int r = wm * 64 + mt * 16 + lrow;
                ldm_x4(aw[mt][0], aw[mt][1], aw[mt][2], aw[mt][3], sw(aA1, r, ch));
            }
            #pragma unroll
            for (int mt = 0; mt < 4; mt++)
                #pragma unroll
                for (int nt = 0; nt < 4; nt++)
                    mma_bf16(acc[mt][nt], aw[mt], bb[nt]);

            // B_lo fragments (reuse bb), pass 3: A_hi @ B_lo
            #pragma unroll
            for (int np = 0; np < 2; np++) {
                const int r = wn * 32 + np * 16 + lrow;
                uint32_t r0, r1, r2, r3;
                ldm_x4(r0, r1, r2, r3, sw(aB1, r, ch));
                bb[2*np][0] = r0; bb[2*np+1][0] = r1;
                bb[2*np][1] = r2; bb[2*np+1][1] = r3;
            }
            #pragma unroll
            for (int mt = 0; mt < 4; mt++)
                #pragma unroll
                for (int nt = 0; nt < 4; nt++)
                    mma_bf16(acc[mt][nt], ah[mt], bb[nt]);
        }

        if (c + 2 < nc) {
            int nb = buf + 2; if (nb >= 3) nb -= 3;
            load_stage(sb + nb * STG_B, Ahi, Alo, Bhi, Blo, K, bm, bn, (c + 2) << 5, tid);
            CP_COMMIT();
        }
        buf = (buf == 2) ? 0 : buf + 1;
        __syncthreads();
    }

    // ---- epilogue ----
    const int tr = lane >> 2;
    const int tc = (lane & 3) * 2;
    if (mode == 0) {
        float* Cb = Cf + (size_t)b * sC;
        #pragma unroll
        for (int mt = 0; mt < 4; mt++) {
            #pragma unroll
            for (int nt = 0; nt < 4; nt++) {
                const int row = bm + wm * 64 + mt * 16 + tr;
                const int col = bn + wn * 32 + nt * 8 + tc;
                float2 v0 = make_float2(acc[mt][nt][0] * scale, acc[mt][nt][1] * scale);
                float2 v1 = make_float2(acc[mt][nt][2] * scale, acc[mt][nt][3] * scale);
                *(float2*)&Cb[(size_t)row * ldc + col]       = v0;
                *(float2*)&Cb[(size_t)(row + 8) * ldc + col] = v1;
            }
        }
    } else {
        bf16* Hb = Chi + (size_t)b * sCbf;
        bf16* Lb = Clo + (size_t)b * sCbf;
        #pragma unroll
        for (int mt = 0; mt < 4; mt++) {
            #pragma unroll
            for (int nt = 0; nt < 4; nt++) {
                const int row = bm + wm * 64 + mt * 16 + tr;
                const int col = bn + wn * 32 + nt * 8 + tc;
                #pragma unroll
                for (int h = 0; h < 2; h++) {
                    float v0 = acc[mt][nt][2*h + 0] * scale;
                    float v1 = acc[mt][nt][2*h + 1] * scale;
                    bf16 h0, l0, h1, l1;
                    split_f32(v0, h0, l0); split_f32(v1, h1, l1);
                    uint32_t hp = (uint32_t)__bfloat16_as_ushort(h0) |
                                  ((uint32_t)__bfloat16_as_ushort(h1) << 16);
                    uint32_t lp = (uint32_t)__bfloat16_as_ushort(l0) |
                                  ((uint32_t)__bfloat16_as_ushort(l1) << 16);
                    *(uint32_t*)&Hb[(size_t)(row + 8*h) * ldc + col] = hp;
                    *(uint32_t*)&Lb[(size_t)(row + 8*h) * ldc + col] = lp;
                }
            }
        }
    }
}

// ===========================================================================
// Causal softmax: reads g_S f32 row (exp cached in regs), writes P as split
// bf16; zero-fill only up to the 256-aligned PV read boundary.
// ===========================================================================
__global__ __launch_bounds__(256)
void softmax_causal_kernel()
{
    const int q = blockIdx.x;
    const int b = blockIdx.y;
    const size_t base = ((size_t)b * SEQ + q) * SEQ;
    const float* row = g_S + base;
    const int len  = q + 1;
    const int wlen = ((q >> 8) + 1) << 8;   // PV reads cols [0, wlen)

    const int tid = threadIdx.x, lane = tid & 31, w = tid >> 5;
    __shared__ float red_max[8], red_sum[8], s_m, s_inv;

    float m = -INFINITY;
    for (int j = tid; j < len; j += 256) m = fmaxf(m, row[j]);
    #pragma unroll
    for (int o = 16; o; o >>= 1) m = fmaxf(m, __shfl_xor_sync(0xffffffffu, m, o));
    if (lane == 0) red_max[w] = m;
    __syncthreads();
    if (w == 0) {
        float v = (lane < 8) ? red_max[lane] : -INFINITY;
        #pragma unroll
        for (int o = 4; o; o >>= 1) v = fmaxf(v, __shfl_xor_sync(0xffffffffu, v, o));
        if (lane == 0) s_m = v;
    }
    __syncthreads();
    m = s_m;

    float e[8];
    float s = 0.0f;
    {
        int idx = 0;
        for (int j = tid; j < len; j += 256, idx++) {
            float v = __expf(row[j] - m);
            e[idx] = v;
            s += v;
        }
    }
    #pragma unroll
    for (int o = 16; o; o >>= 1) s += __shfl_xor_sync(0xffffffffu, s, o);
    if (lane == 0) red_sum[w] = s;
    __syncthreads();
    if (w == 0) {
        float v = (lane < 8) ? red_sum[lane] : 0.0f;
        #pragma unroll
        for (int o = 4; o; o >>= 1) v += __shfl_xor_sync(0xffffffffu, v, o);
        if (lane == 0) s_inv = 1.0f / v;
    }
    __syncthreads();
    const float inv = s_inv;

    {
        int idx = 0;
        for (int j = tid; j < wlen; j += 256) {
            float p;
            if (j < len) { p = e[idx] * inv; idx++; } else p = 0.0f;
            bf16 h, l; split_f32(p, h, l);
            g_Phi[base + j] = h;
            g_Plo[base + j] = l;
        }
    }
}

// ===========================================================================
// Launch
// ===========================================================================
extern "C" void kernel_launch(void* const* d_in, const int* in_sizes, int n_in,
                              void* d_out, int out_size)
{
    const float* x  = (const float*)d_in[0];
    const float* Wq = (const float*)d_in[1];
    const float* Wk = (const float*)d_in[2];
    const float* Wv = (const float*)d_in[3];
    float* out = (float*)d_out;

    cudaFuncSetAttribute(gemm_nt_hmma, cudaFuncAttributeMaxDynamicSharedMemorySize, GEMM_SMEM);

    bf16 *xhi, *xlo, *wthi, *wtlo, *qkvhi, *qkvlo, *Vthi, *Vtlo, *Phi, *Plo;
    float *Sp;
    cudaGetSymbolAddress((void**)&xhi, g_xhi);    cudaGetSymbolAddress((void**)&xlo, g_xlo);
    cudaGetSymbolAddress((void**)&wthi, g_wthi);  cudaGetSymbolAddress((void**)&wtlo, g_wtlo);
    cudaGetSymbolAddress((void**)&qkvhi, g_QKVhi); cudaGetSymbolAddress((void**)&qkvlo, g_QKVlo);
    cudaGetSymbolAddress((void**)&Vthi, g_Vthi);  cudaGetSymbolAddress((void**)&Vtlo, g_Vtlo);
    cudaGetSymbolAddress((void**)&Phi, g_Phi);    cudaGetSymbolAddress((void**)&Plo, g_Plo);
    cudaGetSymbolAddress((void**)&Sp, g_S);

    const size_t WSZ  = (size_t)D_MODEL * DK;
    const size_t QKVS = (size_t)BT * DK;

    // 1) input splits / transposes
    split_kernel<<<(BT * D_MODEL) / (256 * 4), 256>>>(x, xhi, xlo);
    {
        dim3 g(DK / 32, D_MODEL / 32), blk(32, 8);
        wt_split_kernel<<<g, blk>>>(Wq, wthi + 0 * WSZ, wtlo + 0 * WSZ);
        wt_split_kernel<<<g, blk>>>(Wk, wthi + 1 * WSZ, wtlo + 1 * WSZ);
        wt_split_kernel<<<g, blk>>>(Wv, wthi + 2 * WSZ, wtlo + 2 * WSZ);
    }

    // 2) merged QKV projection: z in {0,1,2} selects W and output slice
    {
        dim3 grid(DK / 128, BT / 256, 3);
        gemm_nt_hmma<<<grid, 512, GEMM_SMEM>>>(xhi, xlo, wthi, wtlo,
            D_MODEL, 0, WSZ, 1, 1.0f, 0, 0,
            nullptr, DK, 0, qkvhi, qkvlo, QKVS);
    }

    // 3) V transpose per batch: (t, dk) -> (dk, t)
    {
        dim3 g(DK / 32, SEQ / 32, BATCH), blk(32, 8);
        v_transpose_kernel<<<g, blk>>>(qkvhi + 2 * QKVS, qkvlo + 2 * QKVS, Vthi, Vtlo);
    }

    // 4) scores = (1/32) * Q @ K^T, causal block skip (256-row granularity)
    {
        dim3 grid(SEQ / 128, SEQ / 256, BATCH);
        gemm_nt_hmma<<<grid, 512, GEMM_SMEM>>>(qkvhi, qkvlo, qkvhi + QKVS, qkvlo + QKVS,
            DK, (size_t)SEQ * DK, (size_t)SEQ * DK, 0, 1.0f / 32.0f, 1, 0,
            Sp, SEQ, (size_t)SEQ * SEQ, nullptr, nullptr, 0);
    }

    // 5) causal softmax -> split bf16 P (zero tail to PV boundary)
    softmax_causal_kernel<<<dim3(SEQ, BATCH), 256>>>();

    // 6) out = P @ V  (= P @ (V^T)^T), K truncated per diagonal
    {
        dim3 grid(DK / 128, SEQ / 256, BATCH);
        gemm_nt_hmma<<<grid, 512, GEMM_SMEM>>>(Phi, Plo, Vthi, Vtlo,
            SEQ, (size_t)SEQ * SEQ, (size_t)DK * SEQ, 0, 1.0f, 0, 1,
            out, DK, (size_t)SEQ * DK, nullptr, nullptr, 0);
    }
}

// round 8
// speedup vs baseline: 1.1439x; 1.1136x over previous
#include <cuda_runtime.h>
#include <cuda_bf16.h>
#include <math.h>
#include <stddef.h>
#include <stdint.h>

// Problem constants
#define D_MODEL 1024
#define DK      1024
#define BATCH   4
#define SEQ     2048
#define BT      (BATCH * SEQ)   // 8192

typedef __nv_bfloat16 bf16;

// ===========================================================================
// Scratch (__device__ globals; allocation-free)
// ===========================================================================
__device__ bf16 g_xhi[(size_t)BT * D_MODEL];
__device__ bf16 g_xlo[(size_t)BT * D_MODEL];
__device__ bf16 g_wthi[3][(size_t)D_MODEL * DK];   // W^T, (dk, d_model) K-major
__device__ bf16 g_wtlo[3][(size_t)D_MODEL * DK];
__device__ bf16 g_QKVhi[3][(size_t)BT * DK];       // [0]=Q, [1]=K, [2]=V
__device__ bf16 g_QKVlo[3][(size_t)BT * DK];
__device__ bf16 g_Vthi[(size_t)BATCH * DK * SEQ];  // per batch: (dk, t)
__device__ bf16 g_Vtlo[(size_t)BATCH * DK * SEQ];
__device__ float g_S[(size_t)BATCH * SEQ * SEQ];
__device__ bf16 g_Phi[(size_t)BATCH * SEQ * SEQ];
__device__ bf16 g_Plo[(size_t)BATCH * SEQ * SEQ];

__device__ __forceinline__ void split_f32(float v, bf16& h, bf16& l) {
    h = __float2bfloat16(v);
    l = __float2bfloat16(v - __bfloat162float(h));
}

__device__ __forceinline__ uint32_t smem_to_u32(const void* p) {
    uint32_t a;
    asm("{ .reg .u64 t; cvta.to.shared.u64 t, %1; cvt.u32.u64 %0, t; }" : "=r"(a) : "l"(p));
    return a;
}

__device__ __forceinline__ void ldm_x4(uint32_t& r0, uint32_t& r1, uint32_t& r2, uint32_t& r3,
                                       uint32_t addr) {
    asm volatile("ldmatrix.sync.aligned.m8n8.x4.shared.b16 {%0,%1,%2,%3}, [%4];"
                 : "=r"(r0), "=r"(r1), "=r"(r2), "=r"(r3) : "r"(addr));
}

__device__ __forceinline__ void mma_bf16(float* c, const uint32_t* a, const uint32_t* b) {
    asm volatile("mma.sync.aligned.m16n8k16.row.col.f32.bf16.bf16.f32 "
                 "{%0,%1,%2,%3}, {%4,%5,%6,%7}, {%8,%9}, {%0,%1,%2,%3};"
                 : "+f"(c[0]), "+f"(c[1]), "+f"(c[2]), "+f"(c[3])
                 : "r"(a[0]), "r"(a[1]), "r"(a[2]), "r"(a[3]), "r"(b[0]), "r"(b[1]));
}

#define CP_ASYNC16(dst, src) \
    asm volatile("cp.async.cg.shared.global [%0], [%1], 16;" :: "r"(dst), "l"(src) : "memory")
#define CP_COMMIT() asm volatile("cp.async.commit_group;" ::: "memory")
#define CP_WAIT0()  asm volatile("cp.async.wait_group 0;" ::: "memory")
#define CP_WAIT1()  asm volatile("cp.async.wait_group 1;" ::: "memory")

// Swizzled SMEM address: row*64B, chunk' = chunk ^ ((row>>1)&3) -> conflict-free ldmatrix.
__device__ __forceinline__ uint32_t sw(uint32_t base, int row, int ch) {
    return base + row * 64 + ((ch ^ ((row >> 1) & 3)) << 4);
}

// ===========================================================================
// Elementwise split: f32 -> (hi, lo) bf16
// ===========================================================================
__global__ __launch_bounds__(256)
void split_kernel(const float* __restrict__ in, bf16* __restrict__ hi, bf16* __restrict__ lo)
{
    size_t i = ((size_t)blockIdx.x * 256 + threadIdx.x) * 4;
    float4 v = *(const float4*)(in + i);
    bf16 h0, l0, h1, l1, h2, l2, h3, l3;
    split_f32(v.x, h0, l0); split_f32(v.y, h1, l1);
    split_f32(v.z, h2, l2); split_f32(v.w, h3, l3);
    uint32_t hp0 = (uint32_t)__bfloat16_as_ushort(h0) | ((uint32_t)__bfloat16_as_ushort(h1) << 16);
    uint32_t hp1 = (uint32_t)__bfloat16_as_ushort(h2) | ((uint32_t)__bfloat16_as_ushort(h3) << 16);
    uint32_t lp0 = (uint32_t)__bfloat16_as_ushort(l0) | ((uint32_t)__bfloat16_as_ushort(l1) << 16);
    uint32_t lp1 = (uint32_t)__bfloat16_as_ushort(l2) | ((uint32_t)__bfloat16_as_ushort(l3) << 16);
    *(uint2*)(hi + i) = make_uint2(hp0, hp1);
    *(uint2*)(lo + i) = make_uint2(lp0, lp1);
}

// ===========================================================================
// W (d_model, dk) f32 -> W^T (dk, d_model) split bf16
// ===========================================================================
__global__ __launch_bounds__(256)
void wt_split_kernel(const float* __restrict__ W, bf16* __restrict__ Whi, bf16* __restrict__ Wlo)
{
    __shared__ float tile[32][33];
    int x = blockIdx.x * 32 + threadIdx.x;
    int y = blockIdx.y * 32 + threadIdx.y;
    #pragma unroll
    for (int i = 0; i < 32; i += 8)
        tile[threadIdx.y + i][threadIdx.x] = W[(size_t)(y + i) * DK + x];
    __syncthreads();
    int x2 = blockIdx.y * 32 + threadIdx.x;
    int y2 = blockIdx.x * 32 + threadIdx.y;
    #pragma unroll
    for (int i = 0; i < 32; i += 8) {
        float v = tile[threadIdx.x][threadIdx.y + i];
        bf16 h, l; split_f32(v, h, l);
        Whi[(size_t)(y2 + i) * D_MODEL + x2] = h;
        Wlo[(size_t)(y2 + i) * D_MODEL + x2] = l;
    }
}

// ===========================================================================
// V (t, dk) split bf16 -> V^T (dk, t) split bf16, per batch
// ===========================================================================
__global__ __launch_bounds__(256)
void v_transpose_kernel(const bf16* __restrict__ Vhi, const bf16* __restrict__ Vlo,
                        bf16* __restrict__ Vthi, bf16* __restrict__ Vtlo)
{
    __shared__ bf16 th[32][34];
    __shared__ bf16 tl[32][34];
    const size_t in_base  = (size_t)blockIdx.z * SEQ * DK;
    const size_t out_base = (size_t)blockIdx.z * DK * SEQ;
    int n = blockIdx.x * 32 + threadIdx.x;
    int t = blockIdx.y * 32 + threadIdx.y;
    #pragma unroll
    for (int i = 0; i < 32; i += 8) {
        th[threadIdx.y + i][threadIdx.x] = Vhi[in_base + (size_t)(t + i) * DK + n];
        tl[threadIdx.y + i][threadIdx.x] = Vlo[in_base + (size_t)(t + i) * DK + n];
    }
    __syncthreads();
    int t2 = blockIdx.y * 32 + threadIdx.x;
    int n2 = blockIdx.x * 32 + threadIdx.y;
    #pragma unroll
    for (int i = 0; i < 32; i += 8) {
        Vthi[out_base + (size_t)(n2 + i) * SEQ + t2] = th[threadIdx.x][threadIdx.y + i];
        Vtlo[out_base + (size_t)(n2 + i) * SEQ + t2] = tl[threadIdx.x][threadIdx.y + i];
    }
}

// ===========================================================================
// HMMA split-bf16 GEMM, 128x128 CTA tile, 256 threads, 2 CTAs/SM,
// 3-stage cp.async ring with a SINGLE __syncthreads per chunk.
//   C[M,N] = scale * (A @ B^T); acc = Ah@Bh + Al@Bh + Ah@Bl
//   8 warps (4xM, 2xN), warp tile 32x64, KC=32.
//   mode 0: f32 out * scale; mode 1: split bf16 out (Chi/Clo + z*sCbf)
//   causal: skip CTA if bn > bm+127;  trik: K limited to bm+128.
// ===========================================================================
#define STG_B   32768
#define T_A0    0
#define T_A1    8192
#define T_B0    16384
#define T_B1    24576
#define GEMM_SMEM (3 * STG_B)

__device__ __forceinline__ void load_stage(uint32_t st,
    const bf16* Ahi, const bf16* Alo, const bf16* Bhi, const bf16* Blo,
    int K, int bm, int bn, int k0, int tid)
{
    #pragma unroll
    for (int i = 0; i < 2; i++) {
        const int f = tid + (i << 8);
        const int r = f >> 2;
        const int c = f & 3;
        const uint32_t so = (uint32_t)(r * 64 + ((c ^ ((r >> 1) & 3)) << 4));
        const size_t ga = (size_t)(bm + r) * K + k0 + c * 8;
        const size_t gb = (size_t)(bn + r) * K + k0 + c * 8;
        CP_ASYNC16(st + T_A0 + so, Ahi + ga);
        CP_ASYNC16(st + T_A1 + so, Alo + ga);
        CP_ASYNC16(st + T_B0 + so, Bhi + gb);
        CP_ASYNC16(st + T_B1 + so, Blo + gb);
    }
}

__global__ __launch_bounds__(256, 2)
void gemm_nt_hmma(const bf16* __restrict__ Ahi, const bf16* __restrict__ Alo,
                  const bf16* __restrict__ Bhi, const bf16* __restrict__ Blo,
                  int K, size_t sA, size_t sB,
                  int mode, float scale, int causal, int trik,
                  float* __restrict__ Cf, int ldc, size_t sC,
                  bf16* __restrict__ Chi, bf16* __restrict__ Clo, size_t sCbf)
{
    const int bm = blockIdx.y * 128;
    const int bn = blockIdx.x * 128;
    const int b  = blockIdx.z;
    if (causal && bn > bm + 127) return;

    Ahi += (size_t)b * sA;  Alo += (size_t)b * sA;
    Bhi += (size_t)b * sB;  Blo += (size_t)b * sB;

    extern __shared__ char smem[];
    const uint32_t sb = smem_to_u32(smem);

    const int tid  = threadIdx.x;
    const int lane = tid & 31;
    const int wid  = tid >> 5;
    const int wm   = wid & 3;    // 0..3 -> 32-row slice
    const int wn   = wid >> 2;   // 0..1 -> 64-col slice

    float acc[2][8][4];
    #pragma unroll
    for (int mt = 0; mt < 2; mt++)
        #pragma unroll
        for (int nt = 0; nt < 8; nt++)
            #pragma unroll
            for (int j = 0; j < 4; j++) acc[mt][nt][j] = 0.0f;

    int Keff = trik ? (bm + 128 < K ? bm + 128 : K) : K;
    const int nc = Keff >> 5;   // always >= 4

    // prologue: stages 0, 1
    load_stage(sb + 0 * STG_B, Ahi, Alo, Bhi, Blo, K, bm, bn, 0, tid);
    CP_COMMIT();
    load_stage(sb + 1 * STG_B, Ahi, Alo, Bhi, Blo, K, bm, bn, 32, tid);
    CP_COMMIT();

    int buf = 0;
    for (int c = 0; c < nc; c++) {
        if (c + 1 < nc) CP_WAIT1(); else CP_WAIT0();
        __syncthreads();   // single barrier per chunk: also retires buf (c+2)%3

        // prefetch stage c+2 into the buffer retired at iteration c-1
        if (c + 2 < nc) {
            int nb = buf + 2; if (nb >= 3) nb -= 3;
            load_stage(sb + nb * STG_B, Ahi, Alo, Bhi, Blo, K, bm, bn, (c + 2) << 5, tid);
            CP_COMMIT();
        }

        const uint32_t st  = sb + buf * STG_B;
        const uint32_t aA0 = st + T_A0, aA1 = st + T_A1;
        const uint32_t aB0 = st + T_B0, aB1 = st + T_B1;

        #pragma unroll
        for (int ks = 0; ks < 2; ks++) {
            const int lrow = lane & 15;
            const int ch   = ks * 2 + (lane >> 4);

            uint32_t ah[2][4], aw[2][4], bb[8][2];

            #pragma unroll
            for (int mt = 0; mt < 2; mt++) {
                const int r = wm * 32 + mt * 16 + lrow;
                ldm_x4(ah[mt][0], ah[mt][1], ah[mt][2], ah[mt][3], sw(aA0, r, ch));
                ldm_x4(aw[mt][0], aw[mt][1], aw[mt][2], aw[mt][3], sw(aA1, r, ch));
            }
            #pragma unroll
            for (int np = 0; np < 4; np++) {
                const int r = wn * 64 + np * 16 + lrow;
                uint32_t r0, r1, r2, r3;
                ldm_x4(r0, r1, r2, r3, sw(aB0, r, ch));
                bb[2*np][0] = r0; bb[2*np+1][0] = r1;
                bb[2*np][1] = r2; bb[2*np+1][1] = r3;
            }
            // pass 1: A_hi @ B_hi
            #pragma unroll
            for (int mt = 0; mt < 2; mt++)
                #pragma unroll
                for (int nt = 0; nt < 8; nt++)
                    mma_bf16(acc[mt][nt], ah[mt], bb[nt]);
            // pass 2: A_lo @ B_hi
            #pragma unroll
            for (int mt = 0; mt < 2; mt++)
                #pragma unroll
                for (int nt = 0; nt < 8; nt++)
                    mma_bf16(acc[mt][nt], aw[mt], bb[nt]);

            // B_lo fragments (reuse bb)
            #pragma unroll
            for (int np = 0; np < 4; np++) {
                const int r = wn * 64 + np * 16 + lrow;
                uint32_t r0, r1, r2, r3;
                ldm_x4(r0, r1, r2, r3, sw(aB1, r, ch));
                bb[2*np][0] = r0; bb[2*np+1][0] = r1;
                bb[2*np][1] = r2; bb[2*np+1][1] = r3;
            }
            // pass 3: A_hi @ B_lo
            #pragma unroll
            for (int mt = 0; mt < 2; mt++)
                #pragma unroll
                for (int nt = 0; nt < 8; nt++)
                    mma_bf16(acc[mt][nt], ah[mt], bb[nt]);
        }

        buf = (buf == 2) ? 0 : buf + 1;
    }

    // ---- epilogue ----
    const int tr = lane >> 2;
    const int tc = (lane & 3) * 2;
    if (mode == 0) {
        float* Cb = Cf + (size_t)b * sC;
        #pragma unroll
        for (int mt = 0; mt < 2; mt++) {
            #pragma unroll
            for (int nt = 0; nt < 8; nt++) {
                const int row = bm + wm * 32 + mt * 16 + tr;
                const int col = bn + wn * 64 + nt * 8 + tc;
                float2 v0 = make_float2(acc[mt][nt][0] * scale, acc[mt][nt][1] * scale);
                float2 v1 = make_float2(acc[mt][nt][2] * scale, acc[mt][nt][3] * scale);
                *(float2*)&Cb[(size_t)row * ldc + col]       = v0;
                *(float2*)&Cb[(size_t)(row + 8) * ldc + col] = v1;
            }
        }
    } else {
        bf16* Hb = Chi + (size_t)b * sCbf;
        bf16* Lb = Clo + (size_t)b * sCbf;
        #pragma unroll
        for (int mt = 0; mt < 2; mt++) {
            #pragma unroll
            for (int nt = 0; nt < 8; nt++) {
                const int row = bm + wm * 32 + mt * 16 + tr;
                const int col = bn + wn * 64 + nt * 8 + tc;
                #pragma unroll
                for (int h = 0; h < 2; h++) {
                    float v0 = acc[mt][nt][2*h + 0] * scale;
                    float v1 = acc[mt][nt][2*h + 1] * scale;
                    bf16 h0, l0, h1, l1;
                    split_f32(v0, h0, l0); split_f32(v1, h1, l1);
                    uint32_t hp = (uint32_t)__bfloat16_as_ushort(h0) |
                                  ((uint32_t)__bfloat16_as_ushort(h1) << 16);
                    uint32_t lp = (uint32_t)__bfloat16_as_ushort(l0) |
                                  ((uint32_t)__bfloat16_as_ushort(l1) << 16);
                    *(uint32_t*)&Hb[(size_t)(row + 8*h) * ldc + col] = hp;
                    *(uint32_t*)&Lb[(size_t)(row + 8*h) * ldc + col] = lp;
                }
            }
        }
    }
}

// ===========================================================================
// Causal softmax: reads g_S f32 row (exp cached in regs), writes P as split
// bf16; zero-fill only up to the 128-aligned PV read boundary.
// ===========================================================================
__global__ __launch_bounds__(256)
void softmax_causal_kernel()
{
    const int q = blockIdx.x;
    const int b = blockIdx.y;
    const size_t base = ((size_t)b * SEQ + q) * SEQ;
    const float* row = g_S + base;
    const int len  = q + 1;
    const int wlen = ((q >> 7) + 1) << 7;   // PV reads cols [0, wlen)

    const int tid = threadIdx.x, lane = tid & 31, w = tid >> 5;
    __shared__ float red_max[8], red_sum[8], s_m, s_inv;

    float m = -INFINITY;
    for (int j = tid; j < len; j += 256) m = fmaxf(m, row[j]);
    #pragma unroll
    for (int o = 16; o; o >>= 1) m = fmaxf(m, __shfl_xor_sync(0xffffffffu, m, o));
    if (lane == 0) red_max[w] = m;
    __syncthreads();
    if (w == 0) {
        float v = (lane < 8) ? red_max[lane] : -INFINITY;
        #pragma unroll
        for (int o = 4; o; o >>= 1) v = fmaxf(v, __shfl_xor_sync(0xffffffffu, v, o));
        if (lane == 0) s_m = v;
    }
    __syncthreads();
    m = s_m;

    float e[8];
    float s = 0.0f;
    {
        int idx = 0;
        for (int j = tid; j < len; j += 256, idx++) {
            float v = __expf(row[j] - m);
            e[idx] = v;
            s += v;
        }
    }
    #pragma unroll
    for (int o = 16; o; o >>= 1) s += __shfl_xor_sync(0xffffffffu, s, o);
    if (lane == 0) red_sum[w] = s;
    __syncthreads();
    if (w == 0) {
        float v = (lane < 8) ? red_sum[lane] : 0.0f;
        #pragma unroll
        for (int o = 4; o; o >>= 1) v += __shfl_xor_sync(0xffffffffu, v, o);
        if (lane == 0) s_inv = 1.0f / v;
    }
    __syncthreads();
    const float inv = s_inv;

    {
        int idx = 0;
        for (int j = tid; j < wlen; j += 256) {
            float p;
            if (j < len) { p = e[idx] * inv; idx++; } else p = 0.0f;
            bf16 h, l; split_f32(p, h, l);
            g_Phi[base + j] = h;
            g_Plo[base + j] = l;
        }
    }
}

// ===========================================================================
// Launch
// ===========================================================================
extern "C" void kernel_launch(void* const* d_in, const int* in_sizes, int n_in,
                              void* d_out, int out_size)
{
    const float* x  = (const float*)d_in[0];
    const float* Wq = (const float*)d_in[1];
    const float* Wk = (const float*)d_in[2];
    const float* Wv = (const float*)d_in[3];
    float* out = (float*)d_out;

    cudaFuncSetAttribute(gemm_nt_hmma, cudaFuncAttributeMaxDynamicSharedMemorySize, GEMM_SMEM);

    bf16 *xhi, *xlo, *wthi, *wtlo, *qkvhi, *qkvlo, *Vthi, *Vtlo, *Phi, *Plo;
    float *Sp;
    cudaGetSymbolAddress((void**)&xhi, g_xhi);    cudaGetSymbolAddress((void**)&xlo, g_xlo);
    cudaGetSymbolAddress((void**)&wthi, g_wthi);  cudaGetSymbolAddress((void**)&wtlo, g_wtlo);
    cudaGetSymbolAddress((void**)&qkvhi, g_QKVhi); cudaGetSymbolAddress((void**)&qkvlo, g_QKVlo);
    cudaGetSymbolAddress((void**)&Vthi, g_Vthi);  cudaGetSymbolAddress((void**)&Vtlo, g_Vtlo);
    cudaGetSymbolAddress((void**)&Phi, g_Phi);    cudaGetSymbolAddress((void**)&Plo, g_Plo);
    cudaGetSymbolAddress((void**)&Sp, g_S);

    const size_t WSZ  = (size_t)D_MODEL * DK;
    const size_t QKVS = (size_t)BT * DK;

    // 1) input splits / transposes
    split_kernel<<<(BT * D_MODEL) / (256 * 4), 256>>>(x, xhi, xlo);
    {
        dim3 g(DK / 32, D_MODEL / 32), blk(32, 8);
        wt_split_kernel<<<g, blk>>>(Wq, wthi + 0 * WSZ, wtlo + 0 * WSZ);
        wt_split_kernel<<<g, blk>>>(Wk, wthi + 1 * WSZ, wtlo + 1 * WSZ);
        wt_split_kernel<<<g, blk>>>(Wv, wthi + 2 * WSZ, wtlo + 2 * WSZ);
    }

    // 2) merged QKV projection: z in {0,1,2} selects W and output slice
    {
        dim3 grid(DK / 128, BT / 128, 3);
        gemm_nt_hmma<<<grid, 256, GEMM_SMEM>>>(xhi, xlo, wthi, wtlo,
            D_MODEL, 0, WSZ, 1, 1.0f, 0, 0,
            nullptr, DK, 0, qkvhi, qkvlo, QKVS);
    }

    // 3) V transpose per batch: (t, dk) -> (dk, t)
    {
        dim3 g(DK / 32, SEQ / 32, BATCH), blk(32, 8);
        v_transpose_kernel<<<g, blk>>>(qkvhi + 2 * QKVS, qkvlo + 2 * QKVS, Vthi, Vtlo);
    }

    // 4) scores = (1/32) * Q @ K^T, causal block skip
    {
        dim3 grid(SEQ / 128, SEQ / 128, BATCH);
        gemm_nt_hmma<<<grid, 256, GEMM_SMEM>>>(qkvhi, qkvlo, qkvhi + QKVS, qkvlo + QKVS,
            DK, (size_t)SEQ * DK, (size_t)SEQ * DK, 0, 1.0f / 32.0f, 1, 0,
            Sp, SEQ, (size_t)SEQ * SEQ, nullptr, nullptr, 0);
    }

    // 5) causal softmax -> split bf16 P (zero tail to PV boundary)
    softmax_causal_kernel<<<dim3(SEQ, BATCH), 256>>>();

    // 6) out = P @ V  (= P @ (V^T)^T), K truncated per diagonal
    {
        dim3 grid(DK / 128, SEQ / 128, BATCH);
        gemm_nt_hmma<<<grid, 256, GEMM_SMEM>>>(Phi, Plo, Vthi, Vtlo,
            SEQ, (size_t)SEQ * SEQ, (size_t)DK * SEQ, 0, 1.0f, 0, 1,
            out, DK, (size_t)SEQ * DK, nullptr, nullptr, 0);
    }
}

// round 9
// speedup vs baseline: 1.1498x; 1.0052x over previous
#include <cuda_runtime.h>
#include <cuda_bf16.h>
#include <math.h>
#include <stddef.h>
#include <stdint.h>

// Problem constants
#define D_MODEL 1024
#define DK      1024
#define BATCH   4
#define SEQ     2048
#define BT      (BATCH * SEQ)   // 8192

typedef __nv_bfloat16 bf16;

// ===========================================================================
// Scratch (__device__ globals; allocation-free)
// ===========================================================================
__device__ bf16 g_xhi[(size_t)BT * D_MODEL];
__device__ bf16 g_xlo[(size_t)BT * D_MODEL];
__device__ bf16 g_wthi[3][(size_t)D_MODEL * DK];   // W^T, (dk, d_model) K-major
__device__ bf16 g_wtlo[3][(size_t)D_MODEL * DK];
__device__ bf16 g_QKVhi[3][(size_t)BT * DK];       // [0]=Q, [1]=K, [2]=V
__device__ bf16 g_QKVlo[3][(size_t)BT * DK];
__device__ bf16 g_Vthi[(size_t)BATCH * DK * SEQ];  // per batch: (dk, t)
__device__ bf16 g_Vtlo[(size_t)BATCH * DK * SEQ];
__device__ float g_S[(size_t)BATCH * SEQ * SEQ];
__device__ bf16 g_Phi[(size_t)BATCH * SEQ * SEQ];
__device__ bf16 g_Plo[(size_t)BATCH * SEQ * SEQ];

__device__ __forceinline__ void split_f32(float v, bf16& h, bf16& l) {
    h = __float2bfloat16(v);
    l = __float2bfloat16(v - __bfloat162float(h));
}

__device__ __forceinline__ uint32_t smem_to_u32(const void* p) {
    uint32_t a;
    asm("{ .reg .u64 t; cvta.to.shared.u64 t, %1; cvt.u32.u64 %0, t; }" : "=r"(a) : "l"(p));
    return a;
}

__device__ __forceinline__ void ldm_x4(uint32_t& r0, uint32_t& r1, uint32_t& r2, uint32_t& r3,
                                       uint32_t addr) {
    asm volatile("ldmatrix.sync.aligned.m8n8.x4.shared.b16 {%0,%1,%2,%3}, [%4];"
                 : "=r"(r0), "=r"(r1), "=r"(r2), "=r"(r3) : "r"(addr));
}

__device__ __forceinline__ void mma_bf16(float* c, const uint32_t* a, const uint32_t* b) {
    asm volatile("mma.sync.aligned.m16n8k16.row.col.f32.bf16.bf16.f32 "
                 "{%0,%1,%2,%3}, {%4,%5,%6,%7}, {%8,%9}, {%0,%1,%2,%3};"
                 : "+f"(c[0]), "+f"(c[1]), "+f"(c[2]), "+f"(c[3])
                 : "r"(a[0]), "r"(a[1]), "r"(a[2]), "r"(a[3]), "r"(b[0]), "r"(b[1]));
}

#define CP_ASYNC16(dst, src) \
    asm volatile("cp.async.cg.shared.global [%0], [%1], 16;" :: "r"(dst), "l"(src) : "memory")
#define CP_COMMIT() asm volatile("cp.async.commit_group;" ::: "memory")
#define CP_WAIT0()  asm volatile("cp.async.wait_group 0;" ::: "memory")
#define CP_WAIT1()  asm volatile("cp.async.wait_group 1;" ::: "memory")

// Swizzled SMEM address: row*64B, chunk' = chunk ^ ((row>>1)&3) -> conflict-free ldmatrix.
__device__ __forceinline__ uint32_t sw(uint32_t base, int row, int ch) {
    return base + row * 64 + ((ch ^ ((row >> 1) & 3)) << 4);
}

// ===========================================================================
// Elementwise split: f32 -> (hi, lo) bf16
// ===========================================================================
__global__ __launch_bounds__(256)
void split_kernel(const float* __restrict__ in, bf16* __restrict__ hi, bf16* __restrict__ lo)
{
    size_t i = ((size_t)blockIdx.x * 256 + threadIdx.x) * 4;
    float4 v = *(const float4*)(in + i);
    bf16 h0, l0, h1, l1, h2, l2, h3, l3;
    split_f32(v.x, h0, l0); split_f32(v.y, h1, l1);
    split_f32(v.z, h2, l2); split_f32(v.w, h3, l3);
    uint32_t hp0 = (uint32_t)__bfloat16_as_ushort(h0) | ((uint32_t)__bfloat16_as_ushort(h1) << 16);
    uint32_t hp1 = (uint32_t)__bfloat16_as_ushort(h2) | ((uint32_t)__bfloat16_as_ushort(h3) << 16);
    uint32_t lp0 = (uint32_t)__bfloat16_as_ushort(l0) | ((uint32_t)__bfloat16_as_ushort(l1) << 16);
    uint32_t lp1 = (uint32_t)__bfloat16_as_ushort(l2) | ((uint32_t)__bfloat16_as_ushort(l3) << 16);
    *(uint2*)(hi + i) = make_uint2(hp0, hp1);
    *(uint2*)(lo + i) = make_uint2(lp0, lp1);
}

// ===========================================================================
// W (d_model, dk) f32 -> W^T (dk, d_model) split bf16
// ===========================================================================
__global__ __launch_bounds__(256)
void wt_split_kernel(const float* __restrict__ W, bf16* __restrict__ Whi, bf16* __restrict__ Wlo)
{
    __shared__ float tile[32][33];
    int x = blockIdx.x * 32 + threadIdx.x;
    int y = blockIdx.y * 32 + threadIdx.y;
    #pragma unroll
    for (int i = 0; i < 32; i += 8)
        tile[threadIdx.y + i][threadIdx.x] = W[(size_t)(y + i) * DK + x];
    __syncthreads();
    int x2 = blockIdx.y * 32 + threadIdx.x;
    int y2 = blockIdx.x * 32 + threadIdx.y;
    #pragma unroll
    for (int i = 0; i < 32; i += 8) {
        float v = tile[threadIdx.x][threadIdx.y + i];
        bf16 h, l; split_f32(v, h, l);
        Whi[(size_t)(y2 + i) * D_MODEL + x2] = h;
        Wlo[(size_t)(y2 + i) * D_MODEL + x2] = l;
    }
}

// ===========================================================================
// V (t, dk) split bf16 -> V^T (dk, t) split bf16, per batch
// ===========================================================================
__global__ __launch_bounds__(256)
void v_transpose_kernel(const bf16* __restrict__ Vhi, const bf16* __restrict__ Vlo,
                        bf16* __restrict__ Vthi, bf16* __restrict__ Vtlo)
{
    __shared__ bf16 th[32][34];
    __shared__ bf16 tl[32][34];
    const size_t in_base  = (size_t)blockIdx.z * SEQ * DK;
    const size_t out_base = (size_t)blockIdx.z * DK * SEQ;
    int n = blockIdx.x * 32 + threadIdx.x;
    int t = blockIdx.y * 32 + threadIdx.y;
    #pragma unroll
    for (int i = 0; i < 32; i += 8) {
        th[threadIdx.y + i][threadIdx.x] = Vhi[in_base + (size_t)(t + i) * DK + n];
        tl[threadIdx.y + i][threadIdx.x] = Vlo[in_base + (size_t)(t + i) * DK + n];
    }
    __syncthreads();
    int t2 = blockIdx.y * 32 + threadIdx.x;
    int n2 = blockIdx.x * 32 + threadIdx.y;
    #pragma unroll
    for (int i = 0; i < 32; i += 8) {
        Vthi[out_base + (size_t)(n2 + i) * SEQ + t2] = th[threadIdx.x][threadIdx.y + i];
        Vtlo[out_base + (size_t)(n2 + i) * SEQ + t2] = tl[threadIdx.x][threadIdx.y + i];
    }
}

// ===========================================================================
// HMMA split-bf16 GEMM, 128x128 CTA tile, 256 threads, 2 CTAs/SM,
// 3-stage cp.async ring with a SINGLE __syncthreads per chunk.
//   C[M,N] = scale * (A @ B^T); acc = Ah@Bh + Al@Bh + Ah@Bl
//   8 warps (4xM, 2xN), warp tile 32x64, KC=32.
//   mode 0: f32 out * scale; mode 1: split bf16 out (Chi/Clo + z*sCbf)
//   causal: skip CTA if bn > bm+127;  trik: K limited to bm+128.
// ===========================================================================
#define STG_B   32768
#define T_A0    0
#define T_A1    8192
#define T_B0    16384
#define T_B1    24576
#define GEMM_SMEM (3 * STG_B)

__device__ __forceinline__ void load_stage(uint32_t st,
    const bf16* Ahi, const bf16* Alo, const bf16* Bhi, const bf16* Blo,
    int K, int bm, int bn, int k0, int tid)
{
    #pragma unroll
    for (int i = 0; i < 2; i++) {
        const int f = tid + (i << 8);
        const int r = f >> 2;
        const int c = f & 3;
        const uint32_t so = (uint32_t)(r * 64 + ((c ^ ((r >> 1) & 3)) << 4));
        const size_t ga = (size_t)(bm + r) * K + k0 + c * 8;
        const size_t gb = (size_t)(bn + r) * K + k0 + c * 8;
        CP_ASYNC16(st + T_A0 + so, Ahi + ga);
        CP_ASYNC16(st + T_A1 + so, Alo + ga);
        CP_ASYNC16(st + T_B0 + so, Bhi + gb);
        CP_ASYNC16(st + T_B1 + so, Blo + gb);
    }
}

__global__ __launch_bounds__(256, 2)
void gemm_nt_hmma(const bf16* __restrict__ Ahi, const bf16* __restrict__ Alo,
                  const bf16* __restrict__ Bhi, const bf16* __restrict__ Blo,
                  int K, size_t sA, size_t sB,
                  int mode, float scale, int causal, int trik,
                  float* __restrict__ Cf, int ldc, size_t sC,
                  bf16* __restrict__ Chi, bf16* __restrict__ Clo, size_t sCbf)
{
    const int bm = blockIdx.y * 128;
    const int bn = blockIdx.x * 128;
    const int b  = blockIdx.z;
    if (causal && bn > bm + 127) return;

    Ahi += (size_t)b * sA;  Alo += (size_t)b * sA;
    Bhi += (size_t)b * sB;  Blo += (size_t)b * sB;

    extern __shared__ char smem[];
    const uint32_t sb = smem_to_u32(smem);

    const int tid  = threadIdx.x;
    const int lane = tid & 31;
    const int wid  = tid >> 5;
    const int wm   = wid & 3;    // 0..3 -> 32-row slice
    const int wn   = wid >> 2;   // 0..1 -> 64-col slice

    float acc[2][8][4];
    #pragma unroll
    for (int mt = 0; mt < 2; mt++)
        #pragma unroll
        for (int nt = 0; nt < 8; nt++)
            #pragma unroll
            for (int j = 0; j < 4; j++) acc[mt][nt][j] = 0.0f;

    int Keff = trik ? (bm + 128 < K ? bm + 128 : K) : K;
    const int nc = Keff >> 5;   // always >= 4

    // prologue: stages 0, 1
    load_stage(sb + 0 * STG_B, Ahi, Alo, Bhi, Blo, K, bm, bn, 0, tid);
    CP_COMMIT();
    load_stage(sb + 1 * STG_B, Ahi, Alo, Bhi, Blo, K, bm, bn, 32, tid);
    CP_COMMIT();

    int buf = 0;
    for (int c = 0; c < nc; c++) {
        if (c + 1 < nc) CP_WAIT1(); else CP_WAIT0();
        __syncthreads();   // single barrier per chunk: also retires buf (c+2)%3

        // prefetch stage c+2 into the buffer retired at iteration c-1
        if (c + 2 < nc) {
            int nb = buf + 2; if (nb >= 3) nb -= 3;
            load_stage(sb + nb * STG_B, Ahi, Alo, Bhi, Blo, K, bm, bn, (c + 2) << 5, tid);
            CP_COMMIT();
        }

        const uint32_t st  = sb + buf * STG_B;
        const uint32_t aA0 = st + T_A0, aA1 = st + T_A1;
        const uint32_t aB0 = st + T_B0, aB1 = st + T_B1;

        #pragma unroll
        for (int ks = 0; ks < 2; ks++) {
            const int lrow = lane & 15;
            const int ch   = ks * 2 + (lane >> 4);

            uint32_t ah[2][4], aw[2][4], bb[8][2];

            #pragma unroll
            for (int mt = 0; mt < 2; mt++) {
                const int r = wm * 32 + mt * 16 + lrow;
                ldm_x4(ah[mt][0], ah[mt][1], ah[mt][2], ah[mt][3], sw(aA0, r, ch));
                ldm_x4(aw[mt][0], aw[mt][1], aw[mt][2], aw[mt][3], sw(aA1, r, ch));
            }
            #pragma unroll
            for (int np = 0; np < 4; np++) {
                const int r = wn * 64 + np * 16 + lrow;
                uint32_t r0, r1, r2, r3;
                ldm_x4(r0, r1, r2, r3, sw(aB0, r, ch));
                bb[2*np][0] = r0; bb[2*np+1][0] = r1;
                bb[2*np][1] = r2; bb[2*np+1][1] = r3;
            }
            // pass 1: A_hi @ B_hi
            #pragma unroll
            for (int mt = 0; mt < 2; mt++)
                #pragma unroll
                for (int nt = 0; nt < 8; nt++)
                    mma_bf16(acc[mt][nt], ah[mt], bb[nt]);
            // pass 2: A_lo @ B_hi
            #pragma unroll
            for (int mt = 0; mt < 2; mt++)
                #pragma unroll
                for (int nt = 0; nt < 8; nt++)
                    mma_bf16(acc[mt][nt], aw[mt], bb[nt]);

            // B_lo fragments (reuse bb)
            #pragma unroll
            for (int np = 0; np < 4; np++) {
                const int r = wn * 64 + np * 16 + lrow;
                uint32_t r0, r1, r2, r3;
                ldm_x4(r0, r1, r2, r3, sw(aB1, r, ch));
                bb[2*np][0] = r0; bb[2*np+1][0] = r1;
                bb[2*np][1] = r2; bb[2*np+1][1] = r3;
            }
            // pass 3: A_hi @ B_lo
            #pragma unroll
            for (int mt = 0; mt < 2; mt++)
                #pragma unroll
                for (int nt = 0; nt < 8; nt++)
                    mma_bf16(acc[mt][nt], ah[mt], bb[nt]);
        }

        buf = (buf == 2) ? 0 : buf + 1;
    }

    // ---- epilogue ----
    const int tr = lane >> 2;
    const int tc = (lane & 3) * 2;
    if (mode == 0) {
        float* Cb = Cf + (size_t)b * sC;
        #pragma unroll
        for (int mt = 0; mt < 2; mt++) {
            #pragma unroll
            for (int nt = 0; nt < 8; nt++) {
                const int row = bm + wm * 32 + mt * 16 + tr;
                const int col = bn + wn * 64 + nt * 8 + tc;
                float2 v0 = make_float2(acc[mt][nt][0] * scale, acc[mt][nt][1] * scale);
                float2 v1 = make_float2(acc[mt][nt][2] * scale, acc[mt][nt][3] * scale);
                *(float2*)&Cb[(size_t)row * ldc + col]       = v0;
                *(float2*)&Cb[(size_t)(row + 8) * ldc + col] = v1;
            }
        }
    } else {
        bf16* Hb = Chi + (size_t)b * sCbf;
        bf16* Lb = Clo + (size_t)b * sCbf;
        #pragma unroll
        for (int mt = 0; mt < 2; mt++) {
            #pragma unroll
            for (int nt = 0; nt < 8; nt++) {
                const int row = bm + wm * 32 + mt * 16 + tr;
                const int col = bn + wn * 64 + nt * 8 + tc;
                #pragma unroll
                for (int h = 0; h < 2; h++) {
                    float v0 = acc[mt][nt][2*h + 0] * scale;
                    float v1 = acc[mt][nt][2*h + 1] * scale;
                    bf16 h0, l0, h1, l1;
                    split_f32(v0, h0, l0); split_f32(v1, h1, l1);
                    uint32_t hp = (uint32_t)__bfloat16_as_ushort(h0) |
                                  ((uint32_t)__bfloat16_as_ushort(h1) << 16);
                    uint32_t lp = (uint32_t)__bfloat16_as_ushort(l0) |
                                  ((uint32_t)__bfloat16_as_ushort(l1) << 16);
                    *(uint32_t*)&Hb[(size_t)(row + 8*h) * ldc + col] = hp;
                    *(uint32_t*)&Lb[(size_t)(row + 8*h) * ldc + col] = lp;
                }
            }
        }
    }
}

// ===========================================================================
// Causal softmax: reads g_S f32 row (exp cached in regs), writes P as split
// bf16; zero-fill only up to the 128-aligned PV read boundary.
// ===========================================================================
__global__ __launch_bounds__(256)
void softmax_causal_kernel()
{
    const int q = blockIdx.x;
    const int b = blockIdx.y;
    const size_t base = ((size_t)b * SEQ + q) * SEQ;
    const float* row = g_S + base;
    const int len  = q + 1;
    const int wlen = ((q >> 7) + 1) << 7;   // PV reads cols [0, wlen)

    const int tid = threadIdx.x, lane = tid & 31, w = tid >> 5;
    __shared__ float red_max[8], red_sum[8], s_m, s_inv;

    float m = -INFINITY;
    for (int j = tid; j < len; j += 256) m = fmaxf(m, row[j]);
    #pragma unroll
    for (int o = 16; o; o >>= 1) m = fmaxf(m, __shfl_xor_sync(0xffffffffu, m, o));
    if (lane == 0) red_max[w] = m;
    __syncthreads();
    if (w == 0) {
        float v = (lane < 8) ? red_max[lane] : -INFINITY;
        #pragma unroll
        for (int o = 4; o; o >>= 1) v = fmaxf(v, __shfl_xor_sync(0xffffffffu, v, o));
        if (lane == 0) s_m = v;
    }
    __syncthreads();
    m = s_m;

    float e[8];
    float s = 0.0f;
    {
        int idx = 0;
        for (int j = tid; j < len; j += 256, idx++) {
            float v = __expf(row[j] - m);
            e[idx] = v;
            s += v;
        }
    }
    #pragma unroll
    for (int o = 16; o; o >>= 1) s += __shfl_xor_sync(0xffffffffu, s, o);
    if (lane == 0) red_sum[w] = s;
    __syncthreads();
    if (w == 0) {
        float v = (lane < 8) ? red_sum[lane] : 0.0f;
        #pragma unroll
        for (int o = 4; o; o >>= 1) v += __shfl_xor_sync(0xffffffffu, v, o);
        if (lane == 0) s_inv = 1.0f / v;
    }
    __syncthreads();
    const float inv = s_inv;

    {
        int idx = 0;
        for (int j = tid; j < wlen; j += 256) {
            float p;
            if (j < len) { p = e[idx] * inv; idx++; } else p = 0.0f;
            bf16 h, l; split_f32(p, h, l);
            g_Phi[base + j] = h;
            g_Plo[base + j] = l;
        }
    }
}

// ===========================================================================
// Launch
// ===========================================================================
extern "C" void kernel_launch(void* const* d_in, const int* in_sizes, int n_in,
                              void* d_out, int out_size)
{
    const float* x  = (const float*)d_in[0];
    const float* Wq = (const float*)d_in[1];
    const float* Wk = (const float*)d_in[2];
    const float* Wv = (const float*)d_in[3];
    float* out = (float*)d_out;

    cudaFuncSetAttribute(gemm_nt_hmma, cudaFuncAttributeMaxDynamicSharedMemorySize, GEMM_SMEM);

    bf16 *xhi, *xlo, *wthi, *wtlo, *qkvhi, *qkvlo, *Vthi, *Vtlo, *Phi, *Plo;
    float *Sp;
    cudaGetSymbolAddress((void**)&xhi, g_xhi);    cudaGetSymbolAddress((void**)&xlo, g_xlo);
    cudaGetSymbolAddress((void**)&wthi, g_wthi);  cudaGetSymbolAddress((void**)&wtlo, g_wtlo);
    cudaGetSymbolAddress((void**)&qkvhi, g_QKVhi); cudaGetSymbolAddress((void**)&qkvlo, g_QKVlo);
    cudaGetSymbolAddress((void**)&Vthi, g_Vthi);  cudaGetSymbolAddress((void**)&Vtlo, g_Vtlo);
    cudaGetSymbolAddress((void**)&Phi, g_Phi);    cudaGetSymbolAddress((void**)&Plo, g_Plo);
    cudaGetSymbolAddress((void**)&Sp, g_S);

    const size_t WSZ  = (size_t)D_MODEL * DK;
    const size_t QKVS = (size_t)BT * DK;

    // 1) input splits / transposes
    split_kernel<<<(BT * D_MODEL) / (256 * 4), 256>>>(x, xhi, xlo);
    {
        dim3 g(DK / 32, D_MODEL / 32), blk(32, 8);
        wt_split_kernel<<<g, blk>>>(Wq, wthi + 0 * WSZ, wtlo + 0 * WSZ);
        wt_split_kernel<<<g, blk>>>(Wk, wthi + 1 * WSZ, wtlo + 1 * WSZ);
        wt_split_kernel<<<g, blk>>>(Wv, wthi + 2 * WSZ, wtlo + 2 * WSZ);
    }

    // 2) merged QKV projection: z in {0,1,2} selects W and output slice
    {
        dim3 grid(DK / 128, BT / 128, 3);
        gemm_nt_hmma<<<grid, 256, GEMM_SMEM>>>(xhi, xlo, wthi, wtlo,
            D_MODEL, 0, WSZ, 1, 1.0f, 0, 0,
            nullptr, DK, 0, qkvhi, qkvlo, QKVS);
    }

    // 3) V transpose per batch: (t, dk) -> (dk, t)
    {
        dim3 g(DK / 32, SEQ / 32, BATCH), blk(32, 8);
        v_transpose_kernel<<<g, blk>>>(qkvhi + 2 * QKVS, qkvlo + 2 * QKVS, Vthi, Vtlo);
    }

    // 4) scores = (1/32) * Q @ K^T, causal block skip
    {
        dim3 grid(SEQ / 128, SEQ / 128, BATCH);
        gemm_nt_hmma<<<grid, 256, GEMM_SMEM>>>(qkvhi, qkvlo, qkvhi + QKVS, qkvlo + QKVS,
            DK, (size_t)SEQ * DK, (size_t)SEQ * DK, 0, 1.0f / 32.0f, 1, 0,
            Sp, SEQ, (size_t)SEQ * SEQ, nullptr, nullptr, 0);
    }

    // 5) causal softmax -> split bf16 P (zero tail to PV boundary)
    softmax_causal_kernel<<<dim3(SEQ, BATCH), 256>>>();

    // 6) out = P @ V  (= P @ (V^T)^T), K truncated per diagonal
    {
        dim3 grid(DK / 128, SEQ / 128, BATCH);
        gemm_nt_hmma<<<grid, 256, GEMM_SMEM>>>(Phi, Plo, Vthi, Vtlo,
            SEQ, (size_t)SEQ * SEQ, (size_t)DK * SEQ, 0, 1.0f, 0, 1,
            out, DK, (size_t)SEQ * DK, nullptr, nullptr, 0);
    }
}